// round 1
// baseline (speedup 1.0000x reference)
#include <cuda_runtime.h>
#include <cuda_bf16.h>
#include <math.h>
#include <stdint.h>

// STAttn fused kernel, GB300 sm_103a.
// Shapes: B=32, T=32 (BT=1024), N=64, D=512, H=64, OUT=256.
//
// Kernel 1 (per BT-row CTA, 256 threads):
//   - load x[64][512] fp32 -> split into bf16 hi/lo in smem (one pass over HBM)
//   - h = x @ ue_w^T via mma.sync.m16n8k16 bf16, 3-way split (hi*hi + hi*lo + lo*hi)
//     => fp32-equivalent accuracy (~2^-18 relative), K chunked 4x128 with ue_w
//     split on the fly from L2-resident fp32 weights
//   - epilogue: +bias, leaky_relu(0.2), dot with w_w -> e[64] (smem atomics)
//   - softmax over N=64 (warp 0)
//   - pooled attr[512] = sum_n a[n]*(hi+lo)[n][:] -> scratch
// Kernel 2: fc = attr @ fc1_w^T + fc1_b, written transposed to out[t][b][o].

#define NB 64          // N (nodes per row)
#define DD 512         // D
#define HH 64          // H
#define OUTC 256
#define BT 1024
#define XP 520         // x smem pitch in bf16 (512 + 8 pad -> conflict-free frags)
#define WP 136         // w chunk smem pitch in bf16 (128 + 8 pad)
#define KCHUNK 128

// smem: XH + XL (64*520 bf16 each) + WH + WL (64*136 bf16 each) + 256 floats
#define SMEM1_BF16 (2 * NB * XP + 2 * HH * WP)
#define SMEM1_BYTES (SMEM1_BF16 * 2 + 256 * 4)

__device__ float g_attr[BT * DD];   // 2 MB scratch (static: allocation-free)

__device__ __forceinline__ uint32_t ld_u32(const void* p) {
    return *reinterpret_cast<const uint32_t*>(p);
}

__device__ __forceinline__ void split_bf16(float v, __nv_bfloat16& h, __nv_bfloat16& l) {
    h = __float2bfloat16(v);
    l = __float2bfloat16(v - __bfloat162float(h));
}

__device__ __forceinline__ void mma_bf16(float* d,
                                         uint32_t a0, uint32_t a1, uint32_t a2, uint32_t a3,
                                         uint32_t b0, uint32_t b1) {
    asm volatile(
        "mma.sync.aligned.m16n8k16.row.col.f32.bf16.bf16.f32 "
        "{%0,%1,%2,%3}, {%4,%5,%6,%7}, {%8,%9}, {%0,%1,%2,%3};\n"
        : "+f"(d[0]), "+f"(d[1]), "+f"(d[2]), "+f"(d[3])
        : "r"(a0), "r"(a1), "r"(a2), "r"(a3), "r"(b0), "r"(b1));
}

__global__ __launch_bounds__(256, 1)
void stattn_main(const float* __restrict__ x,
                 const float* __restrict__ ue_w,
                 const float* __restrict__ ue_b,
                 const float* __restrict__ be,
                 const float* __restrict__ w_w) {
    extern __shared__ __nv_bfloat16 sm[];
    __nv_bfloat16* XHs = sm;
    __nv_bfloat16* XLs = sm + NB * XP;
    __nv_bfloat16* WHs = sm + 2 * NB * XP;
    __nv_bfloat16* WLs = WHs + HH * WP;
    float* fbase  = reinterpret_cast<float*>(sm + SMEM1_BF16);
    float* bias_s = fbase;        // 64: ue_b + be
    float* ww_s   = fbase + 64;   // 64: w_w
    float* e_s    = fbase + 128;  // 64: scores
    float* a_s    = fbase + 192;  // 64: softmax weights

    const int tid  = threadIdx.x;
    const int lane = tid & 31;
    const int warp = tid >> 5;
    const int wm   = warp & 3;   // m block (16 rows)
    const int wn   = warp >> 2;  // n block (32 cols)
    const int bt   = blockIdx.x;

    if (tid < 64) {
        e_s[tid]    = 0.0f;
        bias_s[tid] = ue_b[tid] + be[tid];
        ww_s[tid]   = w_w[tid];
    }

    // ---- load x[64][512], split to hi/lo bf16 in smem ----
    const float4* xg = reinterpret_cast<const float4*>(x + (size_t)bt * (NB * DD));
    for (int i = tid; i < NB * (DD / 4); i += 256) {
        int n = i >> 7, c4 = i & 127;
        float4 v = xg[i];
        __nv_bfloat16 h0, h1, h2, h3, l0, l1, l2, l3;
        split_bf16(v.x, h0, l0);
        split_bf16(v.y, h1, l1);
        split_bf16(v.z, h2, l2);
        split_bf16(v.w, h3, l3);
        __nv_bfloat162* ph = reinterpret_cast<__nv_bfloat162*>(XHs + n * XP + c4 * 4);
        ph[0] = __halves2bfloat162(h0, h1);
        ph[1] = __halves2bfloat162(h2, h3);
        __nv_bfloat162* pl = reinterpret_cast<__nv_bfloat162*>(XLs + n * XP + c4 * 4);
        pl[0] = __halves2bfloat162(l0, l1);
        pl[1] = __halves2bfloat162(l2, l3);
    }
    __syncthreads();

    // ---- h GEMM: 64x64, K=512, bf16 hi/lo split (3 products) ----
    float acc[4][4];
#pragma unroll
    for (int i = 0; i < 4; ++i)
#pragma unroll
        for (int j = 0; j < 4; ++j) acc[i][j] = 0.0f;

    const int r  = wm * 16 + (lane >> 2);  // accum row (m / n-of-attn)
    const int qk = (lane & 3) * 2;         // k sub-offset within fragment

    for (int kc = 0; kc < 4; ++kc) {
        if (kc) __syncthreads();  // prev chunk fully consumed
        // load ue_w chunk [64][128] fp32 (L2-resident), split into WH/WL
        for (int i = tid; i < HH * (KCHUNK / 4); i += 256) {
            int j = i >> 5, c4 = i & 31;
            float4 v = *reinterpret_cast<const float4*>(ue_w + j * DD + kc * KCHUNK + c4 * 4);
            __nv_bfloat16 h0, h1, h2, h3, l0, l1, l2, l3;
            split_bf16(v.x, h0, l0);
            split_bf16(v.y, h1, l1);
            split_bf16(v.z, h2, l2);
            split_bf16(v.w, h3, l3);
            __nv_bfloat162* ph = reinterpret_cast<__nv_bfloat162*>(WHs + j * WP + c4 * 4);
            ph[0] = __halves2bfloat162(h0, h1);
            ph[1] = __halves2bfloat162(h2, h3);
            __nv_bfloat162* pl = reinterpret_cast<__nv_bfloat162*>(WLs + j * WP + c4 * 4);
            pl[0] = __halves2bfloat162(l0, l1);
            pl[1] = __halves2bfloat162(l2, l3);
        }
        __syncthreads();

#pragma unroll
        for (int kk = 0; kk < 8; ++kk) {
            const int kg = kc * KCHUNK + kk * 16 + qk;  // global k for A
            const int kl = kk * 16 + qk;                // chunk-local k for B
            const __nv_bfloat16* pa = XHs + r * XP + kg;
            uint32_t ah0 = ld_u32(pa);
            uint32_t ah1 = ld_u32(pa + 8 * XP);
            uint32_t ah2 = ld_u32(pa + 8);
            uint32_t ah3 = ld_u32(pa + 8 * XP + 8);
            const __nv_bfloat16* pal = XLs + r * XP + kg;
            uint32_t al0 = ld_u32(pal);
            uint32_t al1 = ld_u32(pal + 8 * XP);
            uint32_t al2 = ld_u32(pal + 8);
            uint32_t al3 = ld_u32(pal + 8 * XP + 8);
#pragma unroll
            for (int jt = 0; jt < 4; ++jt) {
                const int jb = wn * 32 + jt * 8 + (lane >> 2);
                const __nv_bfloat16* pb  = WHs + jb * WP + kl;
                const __nv_bfloat16* pbl = WLs + jb * WP + kl;
                uint32_t bh0 = ld_u32(pb);
                uint32_t bh1 = ld_u32(pb + 8);
                uint32_t bl0 = ld_u32(pbl);
                uint32_t bl1 = ld_u32(pbl + 8);
                mma_bf16(acc[jt], ah0, ah1, ah2, ah3, bh0, bh1);  // hi*hi
                mma_bf16(acc[jt], ah0, ah1, ah2, ah3, bl0, bl1);  // hi*lo
                mma_bf16(acc[jt], al0, al1, al2, al3, bh0, bh1);  // lo*hi
            }
        }
    }

    // ---- epilogue: bias + leaky_relu(0.2) + dot w_w -> e[64] ----
    // acc[jt] covers rows {r, r+8}, cols {j, j+1} with j = wn*32 + jt*8 + qk
    float pe0 = 0.0f, pe1 = 0.0f;
#pragma unroll
    for (int jt = 0; jt < 4; ++jt) {
        const int j = wn * 32 + jt * 8 + qk;
        float v;
        v = acc[jt][0] + bias_s[j];     v = (v < 0.0f) ? 0.2f * v : v; pe0 = fmaf(ww_s[j],     v, pe0);
        v = acc[jt][1] + bias_s[j + 1]; v = (v < 0.0f) ? 0.2f * v : v; pe0 = fmaf(ww_s[j + 1], v, pe0);
        v = acc[jt][2] + bias_s[j];     v = (v < 0.0f) ? 0.2f * v : v; pe1 = fmaf(ww_s[j],     v, pe1);
        v = acc[jt][3] + bias_s[j + 1]; v = (v < 0.0f) ? 0.2f * v : v; pe1 = fmaf(ww_s[j + 1], v, pe1);
    }
    atomicAdd(&e_s[r], pe0);
    atomicAdd(&e_s[r + 8], pe1);
    __syncthreads();

    // ---- softmax over N=64 (w_b is constant across N -> invariant, dropped) ----
    if (warp == 0) {
        float e0 = e_s[lane], e1 = e_s[lane + 32];
        float mx = fmaxf(e0, e1);
#pragma unroll
        for (int o = 16; o; o >>= 1) mx = fmaxf(mx, __shfl_xor_sync(0xffffffffu, mx, o));
        float x0 = expf(e0 - mx), x1 = expf(e1 - mx);
        float s = x0 + x1;
#pragma unroll
        for (int o = 16; o; o >>= 1) s += __shfl_xor_sync(0xffffffffu, s, o);
        float inv = 1.0f / s;
        a_s[lane]      = x0 * inv;
        a_s[lane + 32] = x1 * inv;
    }
    __syncthreads();

    // ---- pooling: attr[d] = sum_n a[n] * (hi+lo)[n][d]; thread owns d=2*tid,2*tid+1 ----
    float s0 = 0.0f, s1 = 0.0f;
#pragma unroll 4
    for (int n = 0; n < NB; ++n) {
        float an = a_s[n];
        __nv_bfloat162 h = *reinterpret_cast<const __nv_bfloat162*>(XHs + n * XP + 2 * tid);
        __nv_bfloat162 l = *reinterpret_cast<const __nv_bfloat162*>(XLs + n * XP + 2 * tid);
        s0 = fmaf(an, __bfloat162float(h.x) + __bfloat162float(l.x), s0);
        s1 = fmaf(an, __bfloat162float(h.y) + __bfloat162float(l.y), s1);
    }
    *reinterpret_cast<float2*>(g_attr + bt * DD + 2 * tid) = make_float2(s0, s1);
}

// ---- Kernel 2: out[t][b][:] = attr[b*T+t] @ fc1_w^T + fc1_b ----
__global__ __launch_bounds__(128)
void stattn_fc(const float* __restrict__ fc1_w,
               const float* __restrict__ fc1_b,
               float* __restrict__ out) {
    __shared__ float As[32][33];
    __shared__ float Bs[64][33];
    const int tid = threadIdx.x;
    const int tx = tid & 15;   // n dir, 4 cols each
    const int ty = tid >> 4;   // m dir, 4 rows each
    const int m0 = blockIdx.x * 32;
    const int n0 = blockIdx.y * 64;

    float acc[4][4];
#pragma unroll
    for (int i = 0; i < 4; ++i)
#pragma unroll
        for (int j = 0; j < 4; ++j) acc[i][j] = 0.0f;

    for (int kc = 0; kc < 16; ++kc) {
        const int k0 = kc * 32;
        for (int i = tid; i < 32 * 32; i += 128) {
            int m = i >> 5, k = i & 31;
            As[m][k] = g_attr[(m0 + m) * DD + k0 + k];
        }
        for (int i = tid; i < 64 * 32; i += 128) {
            int nn = i >> 5, k = i & 31;
            Bs[nn][k] = fc1_w[(n0 + nn) * DD + k0 + k];
        }
        __syncthreads();
#pragma unroll
        for (int k = 0; k < 32; ++k) {
            float a0 = As[ty * 4 + 0][k], a1 = As[ty * 4 + 1][k];
            float a2 = As[ty * 4 + 2][k], a3 = As[ty * 4 + 3][k];
            float b0 = Bs[tx * 4 + 0][k], b1 = Bs[tx * 4 + 1][k];
            float b2 = Bs[tx * 4 + 2][k], b3 = Bs[tx * 4 + 3][k];
            acc[0][0] = fmaf(a0, b0, acc[0][0]); acc[0][1] = fmaf(a0, b1, acc[0][1]);
            acc[0][2] = fmaf(a0, b2, acc[0][2]); acc[0][3] = fmaf(a0, b3, acc[0][3]);
            acc[1][0] = fmaf(a1, b0, acc[1][0]); acc[1][1] = fmaf(a1, b1, acc[1][1]);
            acc[1][2] = fmaf(a1, b2, acc[1][2]); acc[1][3] = fmaf(a1, b3, acc[1][3]);
            acc[2][0] = fmaf(a2, b0, acc[2][0]); acc[2][1] = fmaf(a2, b1, acc[2][1]);
            acc[2][2] = fmaf(a2, b2, acc[2][2]); acc[2][3] = fmaf(a2, b3, acc[2][3]);
            acc[3][0] = fmaf(a3, b0, acc[3][0]); acc[3][1] = fmaf(a3, b1, acc[3][1]);
            acc[3][2] = fmaf(a3, b2, acc[3][2]); acc[3][3] = fmaf(a3, b3, acc[3][3]);
        }
        __syncthreads();
    }

#pragma unroll
    for (int i = 0; i < 4; ++i) {
        const int btr = m0 + ty * 4 + i;
        const int b = btr >> 5;   // bt = b*T + t, T = 32
        const int t = btr & 31;
        float* orow = out + (size_t)t * (32 * OUTC) + b * OUTC + n0 + tx * 4;
#pragma unroll
        for (int j = 0; j < 4; ++j)
            orow[j] = acc[i][j] + fc1_b[n0 + tx * 4 + j];
    }
}

extern "C" void kernel_launch(void* const* d_in, const int* in_sizes, int n_in,
                              void* d_out, int out_size) {
    const float* x     = (const float*)d_in[0];  // (32,32,64,512)
    const float* ue_w  = (const float*)d_in[1];  // (64,512)
    const float* ue_b  = (const float*)d_in[2];  // (64,)
    const float* be    = (const float*)d_in[3];  // (64,)
    const float* w_w   = (const float*)d_in[4];  // (1,64)
    // d_in[5] = w_b: constant shift of pre-softmax scores -> softmax-invariant
    const float* fc1_w = (const float*)d_in[6];  // (256,512)
    const float* fc1_b = (const float*)d_in[7];  // (256,)
    float* out = (float*)d_out;                  // (32,32,256) as [T][B][OUT]

    cudaFuncSetAttribute(stattn_main, cudaFuncAttributeMaxDynamicSharedMemorySize, SMEM1_BYTES);
    stattn_main<<<BT, 256, SMEM1_BYTES>>>(x, ue_w, ue_b, be, w_w);
    stattn_fc<<<dim3(32, 4), 128>>>(fc1_w, fc1_b, out);
}

// round 2
// speedup vs baseline: 1.8934x; 1.8934x over previous
#include <cuda_runtime.h>
#include <cuda_bf16.h>
#include <math.h>
#include <stdint.h>

// STAttn fused, GB300 sm_103a. Round 2.
// B=32,T=32 (BT=1024), N=64, D=512, H=64, OUT=256.
//
// prep_split : ue_w, fc1_w fp32 -> global bf16 hi/lo (once).
// stattn_main: per-bt CTA. cp.async x[64][512] fp32 -> smem (K-chunk pipelined,
//              depth-2), split-bf16 A-frags on the fly, weights bf16 cp.async
//              double-buffered. 3-product MMA => fp32 accuracy. Epilogue:
//              bias+lrelu+w_w dot -> softmax(N) -> fp32 pooling -> attr bf16
//              hi/lo to global.
// stattn_fc  : 64 CTAs, 64x64 tiles, same 3-product MMA, writes out[t][b][o].

#define NB 64
#define DD 512
#define HH 64
#define OUTC 256
#define BT 1024
#define XPF 524            // fp32 x pitch (512+12): 16B-aligned rows, spread banks
#define WP 136             // bf16 weight-chunk pitch (128+8)
#define AP 520             // bf16 attr pitch in fc kernel (512+8)
#define KCHUNK 128

// main smem: Xs fp32 64*524 | Wbuf[2] (WH+WL 64*136 bf16 each) | 256 floats
#define XS_FLOATS   (NB * XPF)
#define WBUF_BF16   (2 * HH * WP)                  // one buffer: hi+lo
#define SMEM1_BYTES (XS_FLOATS * 4 + 2 * WBUF_BF16 * 2 + 256 * 4)
// fc smem: AH+AL (64*520 bf16 each) | Wbuf[2] | (no float tail needed)
#define SMEMF_BYTES (2 * NB * AP * 2 + 2 * WBUF_BF16 * 2)

__device__ __nv_bfloat16 g_uew_h[HH * DD];
__device__ __nv_bfloat16 g_uew_l[HH * DD];
__device__ __nv_bfloat16 g_fc1_h[OUTC * DD];
__device__ __nv_bfloat16 g_fc1_l[OUTC * DD];
__device__ __nv_bfloat16 g_attr_h[BT * DD];
__device__ __nv_bfloat16 g_attr_l[BT * DD];

// ---------------- helpers ----------------
__device__ __forceinline__ uint32_t ld_u32(const void* p) {
    return *reinterpret_cast<const uint32_t*>(p);
}
__device__ __forceinline__ void cp_async16(uint32_t saddr, const void* g) {
    asm volatile("cp.async.cg.shared.global [%0], [%1], 16;\n" :: "r"(saddr), "l"(g));
}
__device__ __forceinline__ void cp_commit() {
    asm volatile("cp.async.commit_group;\n");
}
template <int N>
__device__ __forceinline__ void cp_wait() {
    asm volatile("cp.async.wait_group %0;\n" :: "n"(N));
}
__device__ __forceinline__ void split1(float v, __nv_bfloat16& h, __nv_bfloat16& l) {
    h = __float2bfloat16(v);
    l = __float2bfloat16(v - __bfloat162float(h));
}
// float2 -> packed bf16x2 hi + packed bf16x2 lo
__device__ __forceinline__ void split2(float2 f, uint32_t& hp, uint32_t& lp) {
    __nv_bfloat16 hx, hy, lx, ly;
    split1(f.x, hx, lx);
    split1(f.y, hy, ly);
    __nv_bfloat162 h2 = __halves2bfloat162(hx, hy);
    __nv_bfloat162 l2 = __halves2bfloat162(lx, ly);
    hp = *reinterpret_cast<uint32_t*>(&h2);
    lp = *reinterpret_cast<uint32_t*>(&l2);
}
__device__ __forceinline__ void mma_bf16(float* d,
                                         uint32_t a0, uint32_t a1, uint32_t a2, uint32_t a3,
                                         uint32_t b0, uint32_t b1) {
    asm volatile(
        "mma.sync.aligned.m16n8k16.row.col.f32.bf16.bf16.f32 "
        "{%0,%1,%2,%3}, {%4,%5,%6,%7}, {%8,%9}, {%0,%1,%2,%3};\n"
        : "+f"(d[0]), "+f"(d[1]), "+f"(d[2]), "+f"(d[3])
        : "r"(a0), "r"(a1), "r"(a2), "r"(a3), "r"(b0), "r"(b1));
}

// ---------------- prep: split weights once ----------------
__global__ __launch_bounds__(256)
void prep_split(const float* __restrict__ ue_w, const float* __restrict__ fc1_w) {
    int i = blockIdx.x * 256 + threadIdx.x;
    if (i < HH * DD) {
        __nv_bfloat16 h, l;
        split1(ue_w[i], h, l);
        g_uew_h[i] = h; g_uew_l[i] = l;
    }
    if (i < OUTC * DD) {
        __nv_bfloat16 h, l;
        split1(fc1_w[i], h, l);
        g_fc1_h[i] = h; g_fc1_l[i] = l;
    }
}

// ---------------- kernel 1 ----------------
__global__ __launch_bounds__(256, 1)
void stattn_main(const float* __restrict__ x,
                 const float* __restrict__ ue_b,
                 const float* __restrict__ be,
                 const float* __restrict__ w_w) {
    extern __shared__ float smf[];
    float* Xs = smf;                                          // 64 x 524 fp32
    __nv_bfloat16* Wb = reinterpret_cast<__nv_bfloat16*>(smf + XS_FLOATS);
    // Wb: buf0 [WH 64*136 | WL 64*136] buf1 [same]
    float* fbase  = reinterpret_cast<float*>(Wb + 2 * WBUF_BF16);
    float* bias_s = fbase;        // 64
    float* ww_s   = fbase + 64;   // 64
    float* e_s    = fbase + 128;  // 64
    float* a_s    = fbase + 192;  // 64

    const int tid  = threadIdx.x;
    const int lane = tid & 31;
    const int warp = tid >> 5;
    const int wm   = warp & 3;
    const int wn   = warp >> 2;
    const int bt   = blockIdx.x;

    if (tid < 64) {
        e_s[tid]    = 0.0f;
        bias_s[tid] = ue_b[tid] + be[tid];
        ww_s[tid]   = w_w[tid];
    }

    const float* xg = x + (size_t)bt * (NB * DD);

    // --- async chunk loaders ---
    auto load_x_chunk = [&](int kc) {
        // 64 rows x 128 floats = 64 x 32 16B-quads
#pragma unroll
        for (int it = 0; it < 8; ++it) {
            int idx = tid + it * 256;
            int n = idx >> 5, q = idx & 31;
            uint32_t s = (uint32_t)__cvta_generic_to_shared(Xs + n * XPF + kc * KCHUNK + q * 4);
            cp_async16(s, xg + n * DD + kc * KCHUNK + q * 4);
        }
    };
    auto load_w_chunk = [&](int kc, int buf) {
        __nv_bfloat16* WH = Wb + buf * WBUF_BF16;
        __nv_bfloat16* WL = WH + HH * WP;
        // hi: 64 rows x 16 quads (8 bf16 each); lo same
#pragma unroll
        for (int it = 0; it < 4; ++it) {
            int idx = tid + it * 256;
            int j = idx >> 4, q = idx & 15;
            uint32_t s = (uint32_t)__cvta_generic_to_shared(WH + j * WP + q * 8);
            cp_async16(s, g_uew_h + j * DD + kc * KCHUNK + q * 8);
        }
#pragma unroll
        for (int it = 0; it < 4; ++it) {
            int idx = tid + it * 256;
            int j = idx >> 4, q = idx & 15;
            uint32_t s = (uint32_t)__cvta_generic_to_shared(WL + j * WP + q * 8);
            cp_async16(s, g_uew_l + j * DD + kc * KCHUNK + q * 8);
        }
    };

    // prologue: groups G0, G1
    load_x_chunk(0); load_w_chunk(0, 0); cp_commit();
    load_x_chunk(1); load_w_chunk(1, 1); cp_commit();

    float acc[4][4];
#pragma unroll
    for (int i = 0; i < 4; ++i)
#pragma unroll
        for (int j = 0; j < 4; ++j) acc[i][j] = 0.0f;

    const int r  = wm * 16 + (lane >> 2);
    const int qk = (lane & 3) * 2;

#pragma unroll
    for (int kc = 0; kc < 4; ++kc) {
        if (kc < 3) cp_wait<1>(); else cp_wait<0>();
        __syncthreads();

        const __nv_bfloat16* WH = Wb + (kc & 1) * WBUF_BF16;
        const __nv_bfloat16* WL = WH + HH * WP;

#pragma unroll
        for (int kk = 0; kk < 8; ++kk) {
            const int kg = kc * KCHUNK + kk * 16 + qk;
            const int kl = kk * 16 + qk;
            float2 f0 = *reinterpret_cast<const float2*>(Xs + r * XPF + kg);
            float2 f1 = *reinterpret_cast<const float2*>(Xs + (r + 8) * XPF + kg);
            float2 f2 = *reinterpret_cast<const float2*>(Xs + r * XPF + kg + 8);
            float2 f3 = *reinterpret_cast<const float2*>(Xs + (r + 8) * XPF + kg + 8);
            uint32_t ah0, ah1, ah2, ah3, al0, al1, al2, al3;
            split2(f0, ah0, al0);
            split2(f1, ah1, al1);
            split2(f2, ah2, al2);
            split2(f3, ah3, al3);
#pragma unroll
            for (int jt = 0; jt < 4; ++jt) {
                const int jb = wn * 32 + jt * 8 + (lane >> 2);
                const __nv_bfloat16* pb  = WH + jb * WP + kl;
                const __nv_bfloat16* pbl = WL + jb * WP + kl;
                uint32_t bh0 = ld_u32(pb);
                uint32_t bh1 = ld_u32(pb + 8);
                uint32_t bl0 = ld_u32(pbl);
                uint32_t bl1 = ld_u32(pbl + 8);
                mma_bf16(acc[jt], ah0, ah1, ah2, ah3, bh0, bh1);  // hi*hi
                mma_bf16(acc[jt], ah0, ah1, ah2, ah3, bl0, bl1);  // hi*lo
                mma_bf16(acc[jt], al0, al1, al2, al3, bh0, bh1);  // lo*hi
            }
        }
        __syncthreads();  // weight buffer fully consumed
        if (kc + 2 < 4) { load_x_chunk(kc + 2); load_w_chunk(kc + 2, kc & 1); cp_commit(); }
    }

    // ---- epilogue: bias + leaky_relu(0.2) + dot w_w -> e[64] ----
    float pe0 = 0.0f, pe1 = 0.0f;
#pragma unroll
    for (int jt = 0; jt < 4; ++jt) {
        const int j = wn * 32 + jt * 8 + qk;
        float v;
        v = acc[jt][0] + bias_s[j];     v = (v < 0.0f) ? 0.2f * v : v; pe0 = fmaf(ww_s[j],     v, pe0);
        v = acc[jt][1] + bias_s[j + 1]; v = (v < 0.0f) ? 0.2f * v : v; pe0 = fmaf(ww_s[j + 1], v, pe0);
        v = acc[jt][2] + bias_s[j];     v = (v < 0.0f) ? 0.2f * v : v; pe1 = fmaf(ww_s[j],     v, pe1);
        v = acc[jt][3] + bias_s[j + 1]; v = (v < 0.0f) ? 0.2f * v : v; pe1 = fmaf(ww_s[j + 1], v, pe1);
    }
    atomicAdd(&e_s[r], pe0);
    atomicAdd(&e_s[r + 8], pe1);
    __syncthreads();

    // ---- softmax over N=64 (w_b is softmax-invariant, dropped) ----
    if (warp == 0) {
        float e0 = e_s[lane], e1 = e_s[lane + 32];
        float mx = fmaxf(e0, e1);
#pragma unroll
        for (int o = 16; o; o >>= 1) mx = fmaxf(mx, __shfl_xor_sync(0xffffffffu, mx, o));
        float x0 = expf(e0 - mx), x1 = expf(e1 - mx);
        float s = x0 + x1;
#pragma unroll
        for (int o = 16; o; o >>= 1) s += __shfl_xor_sync(0xffffffffu, s, o);
        float inv = 1.0f / s;
        a_s[lane]      = x0 * inv;
        a_s[lane + 32] = x1 * inv;
    }
    __syncthreads();

    // ---- pooling over exact fp32 x; store attr as bf16 hi/lo ----
    float s0 = 0.0f, s1 = 0.0f;
#pragma unroll 8
    for (int n = 0; n < NB; ++n) {
        float an = a_s[n];
        float2 v = *reinterpret_cast<const float2*>(Xs + n * XPF + 2 * tid);
        s0 = fmaf(an, v.x, s0);
        s1 = fmaf(an, v.y, s1);
    }
    uint32_t hp, lp;
    split2(make_float2(s0, s1), hp, lp);
    *reinterpret_cast<uint32_t*>(g_attr_h + bt * DD + 2 * tid) = hp;
    *reinterpret_cast<uint32_t*>(g_attr_l + bt * DD + 2 * tid) = lp;
}

// ---------------- kernel 2: fc = attr @ fc1_w^T + b, out[t][b][o] ----------------
__global__ __launch_bounds__(256, 1)
void stattn_fc(const float* __restrict__ fc1_b, float* __restrict__ out) {
    extern __shared__ __nv_bfloat16 smb[];
    __nv_bfloat16* AHs = smb;                 // 64 x 520
    __nv_bfloat16* ALs = smb + NB * AP;
    __nv_bfloat16* Wb  = smb + 2 * NB * AP;   // 2 x (WH 64*136 | WL 64*136)

    const int tid  = threadIdx.x;
    const int lane = tid & 31;
    const int warp = tid >> 5;
    const int wm   = warp & 3;
    const int wn   = warp >> 2;
    const int m0   = blockIdx.x * 64;   // bt tile
    const int n0   = blockIdx.y * 64;   // out-col tile

    auto load_a_chunk = [&](int kc) {
        // hi+lo: 64 rows x 16 quads each
#pragma unroll
        for (int it = 0; it < 4; ++it) {
            int idx = tid + it * 256;
            int n = idx >> 4, q = idx & 15;
            uint32_t s = (uint32_t)__cvta_generic_to_shared(AHs + n * AP + kc * KCHUNK + q * 8);
            cp_async16(s, g_attr_h + (m0 + n) * DD + kc * KCHUNK + q * 8);
        }
#pragma unroll
        for (int it = 0; it < 4; ++it) {
            int idx = tid + it * 256;
            int n = idx >> 4, q = idx & 15;
            uint32_t s = (uint32_t)__cvta_generic_to_shared(ALs + n * AP + kc * KCHUNK + q * 8);
            cp_async16(s, g_attr_l + (m0 + n) * DD + kc * KCHUNK + q * 8);
        }
    };
    auto load_w_chunk = [&](int kc, int buf) {
        __nv_bfloat16* WH = Wb + buf * WBUF_BF16;
        __nv_bfloat16* WL = WH + HH * WP;
#pragma unroll
        for (int it = 0; it < 4; ++it) {
            int idx = tid + it * 256;
            int j = idx >> 4, q = idx & 15;
            uint32_t s = (uint32_t)__cvta_generic_to_shared(WH + j * WP + q * 8);
            cp_async16(s, g_fc1_h + (n0 + j) * DD + kc * KCHUNK + q * 8);
        }
#pragma unroll
        for (int it = 0; it < 4; ++it) {
            int idx = tid + it * 256;
            int j = idx >> 4, q = idx & 15;
            uint32_t s = (uint32_t)__cvta_generic_to_shared(WL + j * WP + q * 8);
            cp_async16(s, g_fc1_l + (n0 + j) * DD + kc * KCHUNK + q * 8);
        }
    };

    load_a_chunk(0); load_w_chunk(0, 0); cp_commit();
    load_a_chunk(1); load_w_chunk(1, 1); cp_commit();

    float acc[4][4];
#pragma unroll
    for (int i = 0; i < 4; ++i)
#pragma unroll
        for (int j = 0; j < 4; ++j) acc[i][j] = 0.0f;

    const int r  = wm * 16 + (lane >> 2);
    const int qk = (lane & 3) * 2;

#pragma unroll
    for (int kc = 0; kc < 4; ++kc) {
        if (kc < 3) cp_wait<1>(); else cp_wait<0>();
        __syncthreads();

        const __nv_bfloat16* WH = Wb + (kc & 1) * WBUF_BF16;
        const __nv_bfloat16* WL = WH + HH * WP;

#pragma unroll
        for (int kk = 0; kk < 8; ++kk) {
            const int kg = kc * KCHUNK + kk * 16 + qk;
            const int kl = kk * 16 + qk;
            const __nv_bfloat16* pa  = AHs + r * AP + kg;
            const __nv_bfloat16* pal = ALs + r * AP + kg;
            uint32_t ah0 = ld_u32(pa);
            uint32_t ah1 = ld_u32(pa + 8 * AP);
            uint32_t ah2 = ld_u32(pa + 8);
            uint32_t ah3 = ld_u32(pa + 8 * AP + 8);
            uint32_t al0 = ld_u32(pal);
            uint32_t al1 = ld_u32(pal + 8 * AP);
            uint32_t al2 = ld_u32(pal + 8);
            uint32_t al3 = ld_u32(pal + 8 * AP + 8);
#pragma unroll
            for (int jt = 0; jt < 4; ++jt) {
                const int jb = wn * 32 + jt * 8 + (lane >> 2);
                const __nv_bfloat16* pb  = WH + jb * WP + kl;
                const __nv_bfloat16* pbl = WL + jb * WP + kl;
                uint32_t bh0 = ld_u32(pb);
                uint32_t bh1 = ld_u32(pb + 8);
                uint32_t bl0 = ld_u32(pbl);
                uint32_t bl1 = ld_u32(pbl + 8);
                mma_bf16(acc[jt], ah0, ah1, ah2, ah3, bh0, bh1);
                mma_bf16(acc[jt], ah0, ah1, ah2, ah3, bl0, bl1);
                mma_bf16(acc[jt], al0, al1, al2, al3, bh0, bh1);
            }
        }
        __syncthreads();
        if (kc + 2 < 4) { load_a_chunk(kc + 2); load_w_chunk(kc + 2, kc & 1); cp_commit(); }
    }

    // epilogue: acc[jt] -> rows {r, r+8} (bt), cols {j, j+1} (out). out[t][b][o].
#pragma unroll
    for (int jt = 0; jt < 4; ++jt) {
        const int j = n0 + wn * 32 + jt * 8 + qk;
        const float b0 = fc1_b[j], b1 = fc1_b[j + 1];
        int btr = m0 + r;
        int b = btr >> 5, t = btr & 31;
        float* o0 = out + ((size_t)t * 32 + b) * OUTC + j;
        o0[0] = acc[jt][0] + b0;
        o0[1] = acc[jt][1] + b1;
        btr = m0 + r + 8;
        b = btr >> 5; t = btr & 31;
        float* o1 = out + ((size_t)t * 32 + b) * OUTC + j;
        o1[0] = acc[jt][2] + b0;
        o1[1] = acc[jt][3] + b1;
    }
}

extern "C" void kernel_launch(void* const* d_in, const int* in_sizes, int n_in,
                              void* d_out, int out_size) {
    const float* x     = (const float*)d_in[0];  // (32,32,64,512)
    const float* ue_w  = (const float*)d_in[1];  // (64,512)
    const float* ue_b  = (const float*)d_in[2];  // (64,)
    const float* be    = (const float*)d_in[3];  // (64,)
    const float* w_w   = (const float*)d_in[4];  // (1,64)
    // d_in[5] = w_b: softmax-invariant, dropped
    const float* fc1_w = (const float*)d_in[6];  // (256,512)
    const float* fc1_b = (const float*)d_in[7];  // (256,)
    float* out = (float*)d_out;                  // [T][B][256]

    prep_split<<<512, 256>>>(ue_w, fc1_w);

    cudaFuncSetAttribute(stattn_main, cudaFuncAttributeMaxDynamicSharedMemorySize, SMEM1_BYTES);
    stattn_main<<<BT, 256, SMEM1_BYTES>>>(x, ue_b, be, w_w);

    cudaFuncSetAttribute(stattn_fc, cudaFuncAttributeMaxDynamicSharedMemorySize, SMEMF_BYTES);
    stattn_fc<<<dim3(16, 4), 256, SMEMF_BYTES>>>(fc1_b, out);
}